// round 7
// baseline (speedup 1.0000x reference)
#include <cuda_runtime.h>
#include <math.h>

#define BB   4
#define CIN  64
#define C2   340
#define HID  170
#define HH   256
#define WW   256
#define NPIX 65536   /* 256*256 */

// ---------------- scratch (device globals; no allocations) ----------------
__device__ float g_xd[BB * CIN * NPIX];          // DCT(x): 67 MB
__device__ float g_yq[BB * C2  * NPIX];          // quant * (W_in @ DCT(x)): 356 MB
__device__ float g_g [BB * HID * NPIX];          // gelu(x1)*x2: 178 MB
__device__ float g_Wt [64  * 384];               // W_in^T  [k][m], stride 384 (zero padded)
__device__ float g_Wot[170 * 64];                // W_out^T [k][m]

// ---------------- tiny transpose of the weight matrices ----------------
__global__ void k_transpose(const float* __restrict__ W_in,
                            const float* __restrict__ W_out) {
    int t = blockIdx.x * blockDim.x + threadIdx.x;
    if (t < C2 * CIN) {               // W_in [340][64] -> g_Wt [64][384]
        int m = t / CIN, k = t % CIN;
        g_Wt[k * 384 + m] = W_in[t];
    }
    if (t < 64 * HID) {               // W_out [64][170] -> g_Wot [170][64]
        int m = t / HID, k = t % HID;
        g_Wot[k * 64 + m] = W_out[t];
    }
}

// ---------------- K1: per-patch 2D DCT of x (64 channels) ----------------
__global__ __launch_bounds__(256) void k_dct(const float* __restrict__ x) {
    __shared__ float Ms[64];
    __shared__ float xs[8 * 256];
    int tid = threadIdx.x;
    if (tid < 64) {
        int i = tid >> 3, j = tid & 7;
        Ms[tid] = (i == 0) ? 0.35355339059327373f
                           : 0.5f * cospif((float)(i * (2 * j + 1)) * (1.0f / 16.0f));
    }
    int pr = blockIdx.x, c = blockIdx.y, b = blockIdx.z;
    const float* src = x + ((size_t)(b * CIN + c) * HH + pr * 8) * WW;
    for (int i = tid; i < 8 * 64; i += 256) {
        int r = i >> 6, q4 = i & 63;
        *(float4*)&xs[r * 256 + q4 * 4] = *(const float4*)(src + r * WW + q4 * 4);
    }
    __syncthreads();
    {   // stage A: column transform (M @ X)
        int col = tid;
        float u[8];
        #pragma unroll
        for (int p = 0; p < 8; p++) u[p] = xs[p * 256 + col];
        #pragma unroll
        for (int i = 0; i < 8; i++) {
            float s = 0.f;
            #pragma unroll
            for (int p = 0; p < 8; p++) s += Ms[i * 8 + p] * u[p];
            xs[i * 256 + col] = s;
        }
    }
    __syncthreads();
    {   // stage B: row transform (T @ M^T), store direct
        float* dst = g_xd + ((size_t)(b * CIN + c) * HH + pr * 8) * WW;
        int row = tid >> 5, pc = tid & 31;
        float4 v0 = *(float4*)&xs[row * 256 + pc * 8];
        float4 v1 = *(float4*)&xs[row * 256 + pc * 8 + 4];
        float u[8] = {v0.x, v0.y, v0.z, v0.w, v1.x, v1.y, v1.z, v1.w};
        float y[8];
        #pragma unroll
        for (int j = 0; j < 8; j++) {
            float s = 0.f;
            #pragma unroll
            for (int q = 0; q < 8; q++) s += u[q] * Ms[j * 8 + q];
            y[j] = s;
        }
        *(float4*)(dst + row * 256 + pc * 8)     = make_float4(y[0], y[1], y[2], y[3]);
        *(float4*)(dst + row * 256 + pc * 8 + 4) = make_float4(y[4], y[5], y[6], y[7]);
    }
}

// ---------------- K2: yq = quant * (W_in @ xd)  (GEMM M=340,K=64,N=65536 per batch)
__global__ __launch_bounds__(256) void k_proj_in(const float* __restrict__ quant) {
    __shared__ float As[64][64];    // [k][m]
    __shared__ float Bs[64][128];   // [k][n]
    int n0 = blockIdx.x * 128;
    int m0 = blockIdx.y * 64;
    int b  = blockIdx.z;
    int tid = threadIdx.x;

    for (int i = tid; i < 64 * 16; i += 256) {
        int k = i >> 4, m4 = i & 15;
        *(float4*)&As[k][m4 * 4] = *(const float4*)(g_Wt + k * 384 + m0 + m4 * 4);
    }
    const float* Bbase = g_xd + (size_t)b * CIN * NPIX + n0;
    for (int i = tid; i < 64 * 32; i += 256) {
        int k = i >> 5, n4 = i & 31;
        *(float4*)&Bs[k][n4 * 4] = *(const float4*)(Bbase + (size_t)k * NPIX + n4 * 4);
    }
    __syncthreads();

    int tmg = tid >> 5, tng = tid & 31;
    float acc[8][4];
    #pragma unroll
    for (int m = 0; m < 8; m++) { acc[m][0] = acc[m][1] = acc[m][2] = acc[m][3] = 0.f; }

    #pragma unroll 8
    for (int k = 0; k < 64; k++) {
        float4 bv = *(float4*)&Bs[k][tng * 4];
        float4 a0 = *(float4*)&As[k][tmg * 8];
        float4 a1 = *(float4*)&As[k][tmg * 8 + 4];
        float a[8] = {a0.x, a0.y, a0.z, a0.w, a1.x, a1.y, a1.z, a1.w};
        #pragma unroll
        for (int m = 0; m < 8; m++) {
            acc[m][0] += a[m] * bv.x; acc[m][1] += a[m] * bv.y;
            acc[m][2] += a[m] * bv.z; acc[m][3] += a[m] * bv.w;
        }
    }

    int fi  = (n0 >> 8) & 7;
    int fjb = (tng & 1) * 4;
    float* dstbase = g_yq + (size_t)b * C2 * NPIX + n0 + tng * 4;
    #pragma unroll
    for (int m = 0; m < 8; m++) {
        int cc = m0 + tmg * 8 + m;
        if (cc < C2) {
            float4 qv = *(const float4*)(quant + cc * 64 + fi * 8 + fjb);
            float4 o = make_float4(acc[m][0] * qv.x, acc[m][1] * qv.y,
                                   acc[m][2] * qv.z, acc[m][3] * qv.w);
            *(float4*)(dstbase + (size_t)cc * NPIX) = o;
        }
    }
}

// ---------------- K3: fused IDCT + depthwise 3x3 + GLU(gelu) -> g ----------------
// __launch_bounds__(512, 2): cap regs at 64 so 2 CTAs co-reside per SM
// (round-5 profile: 94 regs -> 1 CTA/SM -> occ 25%, issue 41%).
__global__ __launch_bounds__(512, 2) void k_fuse(const float* __restrict__ W_dw) {
    extern __shared__ float sm[];
    float* yA  = sm;               // 48 rows * 256
    float* dwA = sm + 48 * 256;    // 32 rows * 256
    __shared__ float Ms[64];
    int tid = threadIdx.x;
    if (tid < 64) {
        int i = tid >> 3, j = tid & 7;
        Ms[tid] = (i == 0) ? 0.35355339059327373f
                           : 0.5f * cospif((float)(i * (2 * j + 1)) * (1.0f / 16.0f));
    }
    int yt = blockIdx.x, c = blockIdx.y, b = blockIdx.z;
    int y0 = yt * 32;

    for (int phase = 0; phase < 2; phase++) {
        int ch = c + phase * HID;
        const float* src = g_yq + (size_t)(b * C2 + ch) * NPIX;
        for (int i = tid; i < 48 * 64; i += 512) {
            int r = i >> 6, q4 = i & 63;
            int gy = y0 - 8 + r;
            float4 v = make_float4(0.f, 0.f, 0.f, 0.f);
            if (gy >= 0 && gy < HH) v = *(const float4*)(src + gy * WW + q4 * 4);
            *(float4*)&yA[r * 256 + q4 * 4] = v;
        }
        __syncthreads();
        // IDCT stage 1: column transform (M^T @ Yq) per patch-row, in place
        for (int i = tid; i < 6 * 256; i += 512) {
            int prow = i >> 8, col = i & 255;
            float u[8];
            #pragma unroll
            for (int p = 0; p < 8; p++) u[p] = yA[(prow * 8 + p) * 256 + col];
            #pragma unroll
            for (int r = 0; r < 8; r++) {
                float s = 0.f;
                #pragma unroll
                for (int p = 0; p < 8; p++) s += Ms[p * 8 + r] * u[p];
                yA[(prow * 8 + r) * 256 + col] = s;
            }
        }
        __syncthreads();
        // IDCT stage 2: row transform (U @ M), in place
        for (int i = tid; i < 48 * 32; i += 512) {
            int row = i >> 5, pc = i & 31;
            float4 v0 = *(float4*)&yA[row * 256 + pc * 8];
            float4 v1 = *(float4*)&yA[row * 256 + pc * 8 + 4];
            float u[8] = {v0.x, v0.y, v0.z, v0.w, v1.x, v1.y, v1.z, v1.w};
            float yv[8];
            #pragma unroll
            for (int j = 0; j < 8; j++) {
                float s = 0.f;
                #pragma unroll
                for (int q = 0; q < 8; q++) s += u[q] * Ms[q * 8 + j];
                yv[j] = s;
            }
            *(float4*)&yA[row * 256 + pc * 8]     = make_float4(yv[0], yv[1], yv[2], yv[3]);
            *(float4*)&yA[row * 256 + pc * 8 + 4] = make_float4(yv[4], yv[5], yv[6], yv[7]);
        }
        __syncthreads();
        // depthwise 3x3, register-blocked 4 px/thread: 18 LDS per 4 px (was 36)
        float w9[9];
        #pragma unroll
        for (int t = 0; t < 9; t++) w9[t] = __ldg(&W_dw[ch * 9 + t]);
        if (phase == 0) {
            for (int g4 = tid; g4 < 32 * 64; g4 += 512) {
                int r = g4 >> 6, w0 = (g4 & 63) * 4;
                float v[3][6];
                #pragma unroll
                for (int dy = 0; dy < 3; dy++) {
                    const float* row = &yA[(r + 7 + dy) * 256];
                    v[dy][0] = (w0 == 0)   ? 0.f : row[w0 - 1];
                    v[dy][1] = row[w0];     v[dy][2] = row[w0 + 1];
                    v[dy][3] = row[w0 + 2]; v[dy][4] = row[w0 + 3];
                    v[dy][5] = (w0 == 252) ? 0.f : row[w0 + 4];
                }
                float s4[4] = {0.f, 0.f, 0.f, 0.f};
                #pragma unroll
                for (int dy = 0; dy < 3; dy++)
                    #pragma unroll
                    for (int dx = 0; dx < 3; dx++) {
                        float wv = w9[dy * 3 + dx];
                        #pragma unroll
                        for (int j = 0; j < 4; j++) s4[j] += wv * v[dy][j + dx];
                    }
                *(float4*)&dwA[r * 256 + w0] = make_float4(s4[0], s4[1], s4[2], s4[3]);
            }
        } else {
            float* gdst = g_g + (size_t)(b * HID + c) * NPIX + (size_t)y0 * WW;
            for (int g4 = tid; g4 < 32 * 64; g4 += 512) {
                int r = g4 >> 6, w0 = (g4 & 63) * 4;
                float v[3][6];
                #pragma unroll
                for (int dy = 0; dy < 3; dy++) {
                    const float* row = &yA[(r + 7 + dy) * 256];
                    v[dy][0] = (w0 == 0)   ? 0.f : row[w0 - 1];
                    v[dy][1] = row[w0];     v[dy][2] = row[w0 + 1];
                    v[dy][3] = row[w0 + 2]; v[dy][4] = row[w0 + 3];
                    v[dy][5] = (w0 == 252) ? 0.f : row[w0 + 4];
                }
                float s4[4] = {0.f, 0.f, 0.f, 0.f};
                #pragma unroll
                for (int dy = 0; dy < 3; dy++)
                    #pragma unroll
                    for (int dx = 0; dx < 3; dx++) {
                        float wv = w9[dy * 3 + dx];
                        #pragma unroll
                        for (int j = 0; j < 4; j++) s4[j] += wv * v[dy][j + dx];
                    }
                float4 x1v = *(float4*)&dwA[r * 256 + w0];
                float o0 = 0.5f * x1v.x * (1.f + erff(x1v.x * 0.70710678118654752f)) * s4[0];
                float o1 = 0.5f * x1v.y * (1.f + erff(x1v.y * 0.70710678118654752f)) * s4[1];
                float o2 = 0.5f * x1v.z * (1.f + erff(x1v.z * 0.70710678118654752f)) * s4[2];
                float o3 = 0.5f * x1v.w * (1.f + erff(x1v.w * 0.70710678118654752f)) * s4[3];
                *(float4*)&gdst[r * 256 + w0] = make_float4(o0, o1, o2, o3);
            }
        }
        __syncthreads();
    }
}

// ---------------- K4: out = W_out @ g  (GEMM M=64, K=170, N=65536 per batch)
__global__ __launch_bounds__(256) void k_proj_out(float* __restrict__ out) {
    __shared__ float As[34][64];
    __shared__ float Bs[34][128];
    int n0 = blockIdx.x * 128, b = blockIdx.y, tid = threadIdx.x;
    int tmg = tid >> 5, tng = tid & 31;
    float acc[8][4];
    #pragma unroll
    for (int m = 0; m < 8; m++) { acc[m][0] = acc[m][1] = acc[m][2] = acc[m][3] = 0.f; }

    for (int kk = 0; kk < HID; kk += 34) {
        for (int i = tid; i < 34 * 16; i += 256) {
            int k = i >> 4, m4 = i & 15;
            *(float4*)&As[k][m4 * 4] = *(const float4*)(g_Wot + (kk + k) * 64 + m4 * 4);
        }
        for (int i = tid; i < 34 * 32; i += 256) {
            int k = i >> 5, n4 = i & 31;
            *(float4*)&Bs[k][n4 * 4] =
                *(const float4*)(g_g + (size_t)(b * HID + kk + k) * NPIX + n0 + n4 * 4);
        }
        __syncthreads();
        #pragma unroll
        for (int k = 0; k < 34; k++) {
            float4 bv = *(float4*)&Bs[k][tng * 4];
            float4 a0 = *(float4*)&As[k][tmg * 8];
            float4 a1 = *(float4*)&As[k][tmg * 8 + 4];
            float a[8] = {a0.x, a0.y, a0.z, a0.w, a1.x, a1.y, a1.z, a1.w};
            #pragma unroll
            for (int m = 0; m < 8; m++) {
                acc[m][0] += a[m] * bv.x; acc[m][1] += a[m] * bv.y;
                acc[m][2] += a[m] * bv.z; acc[m][3] += a[m] * bv.w;
            }
        }
        __syncthreads();
    }
    #pragma unroll
    for (int m = 0; m < 8; m++) {
        *(float4*)(out + (size_t)(b * 64 + tmg * 8 + m) * NPIX + n0 + tng * 4) =
            make_float4(acc[m][0], acc[m][1], acc[m][2], acc[m][3]);
    }
}

// ---------------- launch ----------------
extern "C" void kernel_launch(void* const* d_in, const int* in_sizes, int n_in,
                              void* d_out, int out_size) {
    (void)in_sizes; (void)n_in; (void)out_size;
    const float* x     = (const float*)d_in[0];
    const float* W_in  = (const float*)d_in[1];
    const float* W_dw  = (const float*)d_in[2];
    const float* quant = (const float*)d_in[3];
    const float* W_out = (const float*)d_in[4];
    float* out = (float*)d_out;

    cudaFuncSetAttribute(k_fuse, cudaFuncAttributeMaxDynamicSharedMemorySize,
                         (48 + 32) * 256 * 4);

    k_transpose<<<85, 256>>>(W_in, W_out);
    k_dct<<<dim3(32, 64, 4), 256>>>(x);
    k_proj_in<<<dim3(512, 6, 4), 256>>>(quant);
    k_fuse<<<dim3(8, 170, 4), 512, (48 + 32) * 256 * 4>>>(W_dw);
    k_proj_out<<<dim3(512, 4), 256>>>(out);
}

// round 9
// speedup vs baseline: 1.1355x; 1.1355x over previous
#include <cuda_runtime.h>
#include <math.h>

#define BB   4
#define CIN  64
#define C2   340
#define HID  170
#define HH   256
#define WW   256
#define NPIX 65536   /* 256*256 */

// ---------------- scratch (device globals; no allocations) ----------------
__device__ float g_xd[BB * CIN * NPIX];          // DCT(x): 67 MB
__device__ float g_yq[BB * C2  * NPIX];          // quant * (W_in @ DCT(x)): 356 MB
__device__ float g_g [BB * HID * NPIX];          // gelu(x1)*x2: 178 MB
__device__ float g_Wt [64  * 384];               // W_in^T  [k][m], stride 384 (zero padded)
__device__ float g_Wot[170 * 64];                // W_out^T [k][m]

// ---------------- tiny transpose of the weight matrices ----------------
__global__ void k_transpose(const float* __restrict__ W_in,
                            const float* __restrict__ W_out) {
    int t = blockIdx.x * blockDim.x + threadIdx.x;
    if (t < C2 * CIN) {               // W_in [340][64] -> g_Wt [64][384]
        int m = t / CIN, k = t % CIN;
        g_Wt[k * 384 + m] = W_in[t];
    }
    if (t < 64 * HID) {               // W_out [64][170] -> g_Wot [170][64]
        int m = t / HID, k = t % HID;
        g_Wot[k * 64 + m] = W_out[t];
    }
}

// ---------------- K1: per-patch 2D DCT of x (64 channels) ----------------
__global__ __launch_bounds__(256) void k_dct(const float* __restrict__ x) {
    __shared__ float Ms[64];
    __shared__ float xs[8 * 256];
    int tid = threadIdx.x;
    if (tid < 64) {
        int i = tid >> 3, j = tid & 7;
        Ms[tid] = (i == 0) ? 0.35355339059327373f
                           : 0.5f * cospif((float)(i * (2 * j + 1)) * (1.0f / 16.0f));
    }
    int pr = blockIdx.x, c = blockIdx.y, b = blockIdx.z;
    const float* src = x + ((size_t)(b * CIN + c) * HH + pr * 8) * WW;
    for (int i = tid; i < 8 * 64; i += 256) {
        int r = i >> 6, q4 = i & 63;
        *(float4*)&xs[r * 256 + q4 * 4] = *(const float4*)(src + r * WW + q4 * 4);
    }
    __syncthreads();
    {   // stage A: column transform (M @ X)
        int col = tid;
        float u[8];
        #pragma unroll
        for (int p = 0; p < 8; p++) u[p] = xs[p * 256 + col];
        #pragma unroll
        for (int i = 0; i < 8; i++) {
            float s = 0.f;
            #pragma unroll
            for (int p = 0; p < 8; p++) s += Ms[i * 8 + p] * u[p];
            xs[i * 256 + col] = s;
        }
    }
    __syncthreads();
    {   // stage B: row transform (T @ M^T), store direct
        float* dst = g_xd + ((size_t)(b * CIN + c) * HH + pr * 8) * WW;
        int row = tid >> 5, pc = tid & 31;
        float4 v0 = *(float4*)&xs[row * 256 + pc * 8];
        float4 v1 = *(float4*)&xs[row * 256 + pc * 8 + 4];
        float u[8] = {v0.x, v0.y, v0.z, v0.w, v1.x, v1.y, v1.z, v1.w};
        float y[8];
        #pragma unroll
        for (int j = 0; j < 8; j++) {
            float s = 0.f;
            #pragma unroll
            for (int q = 0; q < 8; q++) s += u[q] * Ms[j * 8 + q];
            y[j] = s;
        }
        *(float4*)(dst + row * 256 + pc * 8)     = make_float4(y[0], y[1], y[2], y[3]);
        *(float4*)(dst + row * 256 + pc * 8 + 4) = make_float4(y[4], y[5], y[6], y[7]);
    }
}

// ---------------- K2: yq = quant * (W_in @ xd)  (GEMM M=340,K=64,N=65536 per batch)
__global__ __launch_bounds__(256) void k_proj_in(const float* __restrict__ quant) {
    __shared__ float As[64][64];    // [k][m]
    __shared__ float Bs[64][128];   // [k][n]
    int n0 = blockIdx.x * 128;
    int m0 = blockIdx.y * 64;
    int b  = blockIdx.z;
    int tid = threadIdx.x;

    for (int i = tid; i < 64 * 16; i += 256) {
        int k = i >> 4, m4 = i & 15;
        *(float4*)&As[k][m4 * 4] = *(const float4*)(g_Wt + k * 384 + m0 + m4 * 4);
    }
    const float* Bbase = g_xd + (size_t)b * CIN * NPIX + n0;
    for (int i = tid; i < 64 * 32; i += 256) {
        int k = i >> 5, n4 = i & 31;
        *(float4*)&Bs[k][n4 * 4] = *(const float4*)(Bbase + (size_t)k * NPIX + n4 * 4);
    }
    __syncthreads();

    int tmg = tid >> 5, tng = tid & 31;
    float acc[8][4];
    #pragma unroll
    for (int m = 0; m < 8; m++) { acc[m][0] = acc[m][1] = acc[m][2] = acc[m][3] = 0.f; }

    #pragma unroll 8
    for (int k = 0; k < 64; k++) {
        float4 bv = *(float4*)&Bs[k][tng * 4];
        float4 a0 = *(float4*)&As[k][tmg * 8];
        float4 a1 = *(float4*)&As[k][tmg * 8 + 4];
        float a[8] = {a0.x, a0.y, a0.z, a0.w, a1.x, a1.y, a1.z, a1.w};
        #pragma unroll
        for (int m = 0; m < 8; m++) {
            acc[m][0] += a[m] * bv.x; acc[m][1] += a[m] * bv.y;
            acc[m][2] += a[m] * bv.z; acc[m][3] += a[m] * bv.w;
        }
    }

    int fi  = (n0 >> 8) & 7;
    int fjb = (tng & 1) * 4;
    float* dstbase = g_yq + (size_t)b * C2 * NPIX + n0 + tng * 4;
    #pragma unroll
    for (int m = 0; m < 8; m++) {
        int cc = m0 + tmg * 8 + m;
        if (cc < C2) {
            float4 qv = *(const float4*)(quant + cc * 64 + fi * 8 + fjb);
            float4 o = make_float4(acc[m][0] * qv.x, acc[m][1] * qv.y,
                                   acc[m][2] * qv.z, acc[m][3] * qv.w);
            *(float4*)(dstbase + (size_t)cc * NPIX) = o;
        }
    }
}

// ---------------- K3: fused IDCT + depthwise 3x3 + GLU(gelu) -> g ----------------
// Dual-channel: rows 0..47 hold channel c (x1), rows 48..95 hold channel c+HID
// (x2). One load, one IDCT stage-1, one IDCT stage-2 pass over all 96 rows ->
// 3 barriers (was 8); dw results combine in registers (no dwA round-trip).
// R8 bug fixed: r & 47 is NOT r % 48 (48 not pow2) -> explicit subtract.
__global__ __launch_bounds__(512) void k_fuse(const float* __restrict__ W_dw) {
    extern __shared__ float sm[];                  // 96 rows * 256 floats = 96 KB
    __shared__ float Ms[64];
    int tid = threadIdx.x;
    if (tid < 64) {
        int i = tid >> 3, j = tid & 7;
        Ms[tid] = (i == 0) ? 0.35355339059327373f
                           : 0.5f * cospif((float)(i * (2 * j + 1)) * (1.0f / 16.0f));
    }
    int yt = blockIdx.x, c = blockIdx.y, b = blockIdx.z;
    int y0 = yt * 32;

    // ---- load both channels (halo rows zero outside image) ----
    const float* src1 = g_yq + (size_t)(b * C2 + c) * NPIX;
    const float* src2 = g_yq + (size_t)(b * C2 + c + HID) * NPIX;
    for (int i = tid; i < 96 * 64; i += 512) {
        int r = i >> 6, q4 = i & 63;
        int rr = (r < 48) ? r : r - 48;            // FIX: explicit mod-48
        const float* src = (r < 48) ? src1 : src2;
        int gy = y0 - 8 + rr;
        float4 v = make_float4(0.f, 0.f, 0.f, 0.f);
        if (gy >= 0 && gy < HH) v = *(const float4*)(src + gy * WW + q4 * 4);
        *(float4*)&sm[r * 256 + q4 * 4] = v;
    }
    __syncthreads();

    // ---- IDCT stage 1: column transform (M^T @ Yq), 12 patch-rows in place ----
    for (int i = tid; i < 12 * 256; i += 512) {
        int prow = i >> 8, col = i & 255;
        float u[8];
        #pragma unroll
        for (int p = 0; p < 8; p++) u[p] = sm[(prow * 8 + p) * 256 + col];
        #pragma unroll
        for (int r = 0; r < 8; r++) {
            float s = 0.f;
            #pragma unroll
            for (int p = 0; p < 8; p++) s += Ms[p * 8 + r] * u[p];
            sm[(prow * 8 + r) * 256 + col] = s;
        }
    }
    __syncthreads();

    // ---- IDCT stage 2: row transform (U @ M), 96 rows in place ----
    for (int i = tid; i < 96 * 32; i += 512) {
        int row = i >> 5, pc = i & 31;
        float4 v0 = *(float4*)&sm[row * 256 + pc * 8];
        float4 v1 = *(float4*)&sm[row * 256 + pc * 8 + 4];
        float u[8] = {v0.x, v0.y, v0.z, v0.w, v1.x, v1.y, v1.z, v1.w};
        float yv[8];
        #pragma unroll
        for (int j = 0; j < 8; j++) {
            float s = 0.f;
            #pragma unroll
            for (int q = 0; q < 8; q++) s += u[q] * Ms[q * 8 + j];
            yv[j] = s;
        }
        *(float4*)&sm[row * 256 + pc * 8]     = make_float4(yv[0], yv[1], yv[2], yv[3]);
        *(float4*)&sm[row * 256 + pc * 8 + 4] = make_float4(yv[4], yv[5], yv[6], yv[7]);
    }
    __syncthreads();

    // ---- depthwise 3x3 on both channels + GLU, straight to gmem ----
    float wA[9], wB[9];
    #pragma unroll
    for (int t = 0; t < 9; t++) wA[t] = __ldg(&W_dw[c * 9 + t]);
    #pragma unroll
    for (int t = 0; t < 9; t++) wB[t] = __ldg(&W_dw[(c + HID) * 9 + t]);

    float* gdst = g_g + (size_t)(b * HID + c) * NPIX + (size_t)y0 * WW;
    for (int g4 = tid; g4 < 32 * 64; g4 += 512) {
        int r = g4 >> 6, w0 = (g4 & 63) * 4;
        float s1[4] = {0.f, 0.f, 0.f, 0.f};
        float s2[4] = {0.f, 0.f, 0.f, 0.f};
        #pragma unroll
        for (int dy = 0; dy < 3; dy++) {
            const float* rowA = &sm[(r + 7 + dy) * 256];
            const float* rowB = rowA + 48 * 256;
            float vA[6], vB[6];
            vA[0] = (w0 == 0)   ? 0.f : rowA[w0 - 1];
            vA[1] = rowA[w0];     vA[2] = rowA[w0 + 1];
            vA[3] = rowA[w0 + 2]; vA[4] = rowA[w0 + 3];
            vA[5] = (w0 == 252) ? 0.f : rowA[w0 + 4];
            vB[0] = (w0 == 0)   ? 0.f : rowB[w0 - 1];
            vB[1] = rowB[w0];     vB[2] = rowB[w0 + 1];
            vB[3] = rowB[w0 + 2]; vB[4] = rowB[w0 + 3];
            vB[5] = (w0 == 252) ? 0.f : rowB[w0 + 4];
            #pragma unroll
            for (int dx = 0; dx < 3; dx++) {
                float wa = wA[dy * 3 + dx], wb = wB[dy * 3 + dx];
                #pragma unroll
                for (int j = 0; j < 4; j++) {
                    s1[j] += wa * vA[j + dx];
                    s2[j] += wb * vB[j + dx];
                }
            }
        }
        float o[4];
        #pragma unroll
        for (int j = 0; j < 4; j++)
            o[j] = 0.5f * s1[j] * (1.f + erff(s1[j] * 0.70710678118654752f)) * s2[j];
        *(float4*)&gdst[r * 256 + w0] = make_float4(o[0], o[1], o[2], o[3]);
    }
}

// ---------------- K4: out = W_out @ g  (GEMM M=64, K=170, N=65536 per batch)
__global__ __launch_bounds__(256) void k_proj_out(float* __restrict__ out) {
    __shared__ float As[34][64];
    __shared__ float Bs[34][128];
    int n0 = blockIdx.x * 128, b = blockIdx.y, tid = threadIdx.x;
    int tmg = tid >> 5, tng = tid & 31;
    float acc[8][4];
    #pragma unroll
    for (int m = 0; m < 8; m++) { acc[m][0] = acc[m][1] = acc[m][2] = acc[m][3] = 0.f; }

    for (int kk = 0; kk < HID; kk += 34) {
        for (int i = tid; i < 34 * 16; i += 256) {
            int k = i >> 4, m4 = i & 15;
            *(float4*)&As[k][m4 * 4] = *(const float4*)(g_Wot + (kk + k) * 64 + m4 * 4);
        }
        for (int i = tid; i < 34 * 32; i += 256) {
            int k = i >> 5, n4 = i & 31;
            *(float4*)&Bs[k][n4 * 4] =
                *(const float4*)(g_g + (size_t)(b * HID + kk + k) * NPIX + n0 + n4 * 4);
        }
        __syncthreads();
        #pragma unroll
        for (int k = 0; k < 34; k++) {
            float4 bv = *(float4*)&Bs[k][tng * 4];
            float4 a0 = *(float4*)&As[k][tmg * 8];
            float4 a1 = *(float4*)&As[k][tmg * 8 + 4];
            float a[8] = {a0.x, a0.y, a0.z, a0.w, a1.x, a1.y, a1.z, a1.w};
            #pragma unroll
            for (int m = 0; m < 8; m++) {
                acc[m][0] += a[m] * bv.x; acc[m][1] += a[m] * bv.y;
                acc[m][2] += a[m] * bv.z; acc[m][3] += a[m] * bv.w;
            }
        }
        __syncthreads();
    }
    #pragma unroll
    for (int m = 0; m < 8; m++) {
        *(float4*)(out + (size_t)(b * 64 + tmg * 8 + m) * NPIX + n0 + tng * 4) =
            make_float4(acc[m][0], acc[m][1], acc[m][2], acc[m][3]);
    }
}

// ---------------- launch ----------------
extern "C" void kernel_launch(void* const* d_in, const int* in_sizes, int n_in,
                              void* d_out, int out_size) {
    (void)in_sizes; (void)n_in; (void)out_size;
    const float* x     = (const float*)d_in[0];
    const float* W_in  = (const float*)d_in[1];
    const float* W_dw  = (const float*)d_in[2];
    const float* quant = (const float*)d_in[3];
    const float* W_out = (const float*)d_in[4];
    float* out = (float*)d_out;

    cudaFuncSetAttribute(k_fuse, cudaFuncAttributeMaxDynamicSharedMemorySize,
                         96 * 256 * 4);

    k_transpose<<<85, 256>>>(W_in, W_out);
    k_dct<<<dim3(32, 64, 4), 256>>>(x);
    k_proj_in<<<dim3(512, 6, 4), 256>>>(quant);
    k_fuse<<<dim3(8, 170, 4), 512, 96 * 256 * 4>>>(W_dw);
    k_proj_out<<<dim3(512, 4), 256>>>(out);
}

// round 10
// speedup vs baseline: 1.4480x; 1.2752x over previous
#include <cuda_runtime.h>
#include <math.h>

#define BB   4
#define CIN  64
#define C2   340
#define HID  170
#define HH   256
#define WW   256
#define NPIX 65536   /* 256*256 */

// ---------------- scratch (device globals; no allocations) ----------------
__device__ float g_xd[BB * CIN * NPIX];          // DCT(x): 67 MB
__device__ float g_yq[BB * C2  * NPIX];          // quant * (W_in @ DCT(x)): 356 MB
__device__ float g_g [BB * HID * NPIX];          // gelu(x1)*x2: 178 MB
__device__ float g_Wt [64  * 384];               // W_in^T  [k][m], stride 384 (zero padded)
__device__ float g_Wot[170 * 64];                // W_out^T [k][m]

// ---------------- tiny transpose of the weight matrices ----------------
__global__ void k_transpose(const float* __restrict__ W_in,
                            const float* __restrict__ W_out) {
    int t = blockIdx.x * blockDim.x + threadIdx.x;
    if (t < C2 * CIN) {               // W_in [340][64] -> g_Wt [64][384]
        int m = t / CIN, k = t % CIN;
        g_Wt[k * 384 + m] = W_in[t];
    }
    if (t < 64 * HID) {               // W_out [64][170] -> g_Wot [170][64]
        int m = t / HID, k = t % HID;
        g_Wot[k * 64 + m] = W_out[t];
    }
}

// ---------------- K1: per-patch 2D DCT of x (64 channels) ----------------
__global__ __launch_bounds__(256) void k_dct(const float* __restrict__ x) {
    __shared__ float Ms[64];
    __shared__ float xs[8 * 256];
    int tid = threadIdx.x;
    if (tid < 64) {
        int i = tid >> 3, j = tid & 7;
        Ms[tid] = (i == 0) ? 0.35355339059327373f
                           : 0.5f * cospif((float)(i * (2 * j + 1)) * (1.0f / 16.0f));
    }
    int pr = blockIdx.x, c = blockIdx.y, b = blockIdx.z;
    const float* src = x + ((size_t)(b * CIN + c) * HH + pr * 8) * WW;
    for (int i = tid; i < 8 * 64; i += 256) {
        int r = i >> 6, q4 = i & 63;
        *(float4*)&xs[r * 256 + q4 * 4] = *(const float4*)(src + r * WW + q4 * 4);
    }
    __syncthreads();
    {   // stage A: column transform (M @ X)
        int col = tid;
        float u[8];
        #pragma unroll
        for (int p = 0; p < 8; p++) u[p] = xs[p * 256 + col];
        #pragma unroll
        for (int i = 0; i < 8; i++) {
            float s = 0.f;
            #pragma unroll
            for (int p = 0; p < 8; p++) s += Ms[i * 8 + p] * u[p];
            xs[i * 256 + col] = s;
        }
    }
    __syncthreads();
    {   // stage B: row transform (T @ M^T), store direct
        float* dst = g_xd + ((size_t)(b * CIN + c) * HH + pr * 8) * WW;
        int row = tid >> 5, pc = tid & 31;
        float4 v0 = *(float4*)&xs[row * 256 + pc * 8];
        float4 v1 = *(float4*)&xs[row * 256 + pc * 8 + 4];
        float u[8] = {v0.x, v0.y, v0.z, v0.w, v1.x, v1.y, v1.z, v1.w};
        float y[8];
        #pragma unroll
        for (int j = 0; j < 8; j++) {
            float s = 0.f;
            #pragma unroll
            for (int q = 0; q < 8; q++) s += u[q] * Ms[j * 8 + q];
            y[j] = s;
        }
        *(float4*)(dst + row * 256 + pc * 8)     = make_float4(y[0], y[1], y[2], y[3]);
        *(float4*)(dst + row * 256 + pc * 8 + 4) = make_float4(y[4], y[5], y[6], y[7]);
    }
}

// ---------------- K2: yq = quant * (W_in @ xd)  (GEMM M=340,K=64,N=65536 per batch)
__global__ __launch_bounds__(256) void k_proj_in(const float* __restrict__ quant) {
    __shared__ float As[64][64];    // [k][m]
    __shared__ float Bs[64][128];   // [k][n]
    int n0 = blockIdx.x * 128;
    int m0 = blockIdx.y * 64;
    int b  = blockIdx.z;
    int tid = threadIdx.x;

    for (int i = tid; i < 64 * 16; i += 256) {
        int k = i >> 4, m4 = i & 15;
        *(float4*)&As[k][m4 * 4] = *(const float4*)(g_Wt + k * 384 + m0 + m4 * 4);
    }
    const float* Bbase = g_xd + (size_t)b * CIN * NPIX + n0;
    for (int i = tid; i < 64 * 32; i += 256) {
        int k = i >> 5, n4 = i & 31;
        *(float4*)&Bs[k][n4 * 4] = *(const float4*)(Bbase + (size_t)k * NPIX + n4 * 4);
    }
    __syncthreads();

    int tmg = tid >> 5, tng = tid & 31;
    float acc[8][4];
    #pragma unroll
    for (int m = 0; m < 8; m++) { acc[m][0] = acc[m][1] = acc[m][2] = acc[m][3] = 0.f; }

    #pragma unroll 8
    for (int k = 0; k < 64; k++) {
        float4 bv = *(float4*)&Bs[k][tng * 4];
        float4 a0 = *(float4*)&As[k][tmg * 8];
        float4 a1 = *(float4*)&As[k][tmg * 8 + 4];
        float a[8] = {a0.x, a0.y, a0.z, a0.w, a1.x, a1.y, a1.z, a1.w};
        #pragma unroll
        for (int m = 0; m < 8; m++) {
            acc[m][0] += a[m] * bv.x; acc[m][1] += a[m] * bv.y;
            acc[m][2] += a[m] * bv.z; acc[m][3] += a[m] * bv.w;
        }
    }

    int fi  = (n0 >> 8) & 7;
    int fjb = (tng & 1) * 4;
    float* dstbase = g_yq + (size_t)b * C2 * NPIX + n0 + tng * 4;
    #pragma unroll
    for (int m = 0; m < 8; m++) {
        int cc = m0 + tmg * 8 + m;
        if (cc < C2) {
            float4 qv = *(const float4*)(quant + cc * 64 + fi * 8 + fjb);
            float4 o = make_float4(acc[m][0] * qv.x, acc[m][1] * qv.y,
                                   acc[m][2] * qv.z, acc[m][3] * qv.w);
            *(float4*)(dstbase + (size_t)cc * NPIX) = o;
        }
    }
}

// ---------------- K3: fused IDCT + depthwise 3x3 + GLU(gelu) -> g ----------------
// Register-resident per-patch IDCT: each of 384 threads owns one 8x8 patch
// (2 channels x 6 patch-rows x 32 patch-cols), loads it straight from gmem,
// does the full 2D IDCT in registers (no smem round-trips), and writes only
// the finished spatial values to the 96-row smem arena. One barrier, then the
// dual-channel dw3x3 + GLU stage (R9 code, stride 384).
__global__ __launch_bounds__(384) void k_fuse(const float* __restrict__ W_dw) {
    extern __shared__ float sm[];                  // 96 rows * 256 floats = 96 KB
    __shared__ float Ms[64];
    int tid = threadIdx.x;
    if (tid < 64) {
        int i = tid >> 3, j = tid & 7;
        Ms[tid] = (i == 0) ? 0.35355339059327373f
                           : 0.5f * cospif((float)(i * (2 * j + 1)) * (1.0f / 16.0f));
    }
    __syncthreads();

    int yt = blockIdx.x, c = blockIdx.y, b = blockIdx.z;
    int y0 = yt * 32;

    // ---- per-thread patch: gmem -> registers -> full 2D IDCT -> smem ----
    {
        int ch  = tid / 192;                       // 0: x1 (c), 1: x2 (c+HID)
        int rem = tid - ch * 192;
        int pr  = rem >> 5;                        // 0..5 (patch-row within arena)
        int pc  = rem & 31;                        // 0..31 (patch-col)
        const float* src = g_yq + (size_t)(b * C2 + c + ch * HID) * NPIX;
        int gy0 = y0 - 8 + pr * 8;                 // 8-aligned: patch fully in or out
        float v[8][8];
        if (gy0 >= 0 && gy0 < HH) {
            #pragma unroll
            for (int p = 0; p < 8; p++) {
                const float* row = src + (size_t)(gy0 + p) * WW + pc * 8;
                float4 a = *(const float4*)row;
                float4 d = *(const float4*)(row + 4);
                v[p][0] = a.x; v[p][1] = a.y; v[p][2] = a.z; v[p][3] = a.w;
                v[p][4] = d.x; v[p][5] = d.y; v[p][6] = d.z; v[p][7] = d.w;
            }
            // column transform: v[:,j] <- M^T @ v[:,j]
            #pragma unroll
            for (int j = 0; j < 8; j++) {
                float u[8];
                #pragma unroll
                for (int p = 0; p < 8; p++) u[p] = v[p][j];
                #pragma unroll
                for (int r = 0; r < 8; r++) {
                    float s = 0.f;
                    #pragma unroll
                    for (int p = 0; p < 8; p++) s += Ms[p * 8 + r] * u[p];
                    v[r][j] = s;
                }
            }
            // row transform: v[r,:] <- v[r,:] @ M
            #pragma unroll
            for (int r = 0; r < 8; r++) {
                float u[8];
                #pragma unroll
                for (int q = 0; q < 8; q++) u[q] = v[r][q];
                #pragma unroll
                for (int j = 0; j < 8; j++) {
                    float s = 0.f;
                    #pragma unroll
                    for (int q = 0; q < 8; q++) s += u[q] * Ms[q * 8 + j];
                    v[r][j] = s;
                }
            }
        } else {
            #pragma unroll
            for (int p = 0; p < 8; p++)
                #pragma unroll
                for (int j = 0; j < 8; j++) v[p][j] = 0.f;
        }
        float* dst = &sm[(ch * 48 + pr * 8) * 256 + pc * 8];
        #pragma unroll
        for (int r = 0; r < 8; r++) {
            *(float4*)(dst + r * 256)     = make_float4(v[r][0], v[r][1], v[r][2], v[r][3]);
            *(float4*)(dst + r * 256 + 4) = make_float4(v[r][4], v[r][5], v[r][6], v[r][7]);
        }
    }
    __syncthreads();

    // ---- depthwise 3x3 on both channels + GLU, straight to gmem ----
    float wA[9], wB[9];
    #pragma unroll
    for (int t = 0; t < 9; t++) wA[t] = __ldg(&W_dw[c * 9 + t]);
    #pragma unroll
    for (int t = 0; t < 9; t++) wB[t] = __ldg(&W_dw[(c + HID) * 9 + t]);

    float* gdst = g_g + (size_t)(b * HID + c) * NPIX + (size_t)y0 * WW;
    for (int g4 = tid; g4 < 32 * 64; g4 += 384) {
        int r = g4 >> 6, w0 = (g4 & 63) * 4;
        float s1[4] = {0.f, 0.f, 0.f, 0.f};
        float s2[4] = {0.f, 0.f, 0.f, 0.f};
        #pragma unroll
        for (int dy = 0; dy < 3; dy++) {
            const float* rowA = &sm[(r + 7 + dy) * 256];
            const float* rowB = rowA + 48 * 256;
            float vA[6], vB[6];
            vA[0] = (w0 == 0)   ? 0.f : rowA[w0 - 1];
            vA[1] = rowA[w0];     vA[2] = rowA[w0 + 1];
            vA[3] = rowA[w0 + 2]; vA[4] = rowA[w0 + 3];
            vA[5] = (w0 == 252) ? 0.f : rowA[w0 + 4];
            vB[0] = (w0 == 0)   ? 0.f : rowB[w0 - 1];
            vB[1] = rowB[w0];     vB[2] = rowB[w0 + 1];
            vB[3] = rowB[w0 + 2]; vB[4] = rowB[w0 + 3];
            vB[5] = (w0 == 252) ? 0.f : rowB[w0 + 4];
            #pragma unroll
            for (int dx = 0; dx < 3; dx++) {
                float wa = wA[dy * 3 + dx], wb = wB[dy * 3 + dx];
                #pragma unroll
                for (int j = 0; j < 4; j++) {
                    s1[j] += wa * vA[j + dx];
                    s2[j] += wb * vB[j + dx];
                }
            }
        }
        float o[4];
        #pragma unroll
        for (int j = 0; j < 4; j++)
            o[j] = 0.5f * s1[j] * (1.f + erff(s1[j] * 0.70710678118654752f)) * s2[j];
        *(float4*)&gdst[r * 256 + w0] = make_float4(o[0], o[1], o[2], o[3]);
    }
}

// ---------------- K4: out = W_out @ g  (GEMM M=64, K=170, N=65536 per batch)
__global__ __launch_bounds__(256) void k_proj_out(float* __restrict__ out) {
    __shared__ float As[34][64];
    __shared__ float Bs[34][128];
    int n0 = blockIdx.x * 128, b = blockIdx.y, tid = threadIdx.x;
    int tmg = tid >> 5, tng = tid & 31;
    float acc[8][4];
    #pragma unroll
    for (int m = 0; m < 8; m++) { acc[m][0] = acc[m][1] = acc[m][2] = acc[m][3] = 0.f; }

    for (int kk = 0; kk < HID; kk += 34) {
        for (int i = tid; i < 34 * 16; i += 256) {
            int k = i >> 4, m4 = i & 15;
            *(float4*)&As[k][m4 * 4] = *(const float4*)(g_Wot + (kk + k) * 64 + m4 * 4);
        }
        for (int i = tid; i < 34 * 32; i += 256) {
            int k = i >> 5, n4 = i & 31;
            *(float4*)&Bs[k][n4 * 4] =
                *(const float4*)(g_g + (size_t)(b * HID + kk + k) * NPIX + n0 + n4 * 4);
        }
        __syncthreads();
        #pragma unroll
        for (int k = 0; k < 34; k++) {
            float4 bv = *(float4*)&Bs[k][tng * 4];
            float4 a0 = *(float4*)&As[k][tmg * 8];
            float4 a1 = *(float4*)&As[k][tmg * 8 + 4];
            float a[8] = {a0.x, a0.y, a0.z, a0.w, a1.x, a1.y, a1.z, a1.w};
            #pragma unroll
            for (int m = 0; m < 8; m++) {
                acc[m][0] += a[m] * bv.x; acc[m][1] += a[m] * bv.y;
                acc[m][2] += a[m] * bv.z; acc[m][3] += a[m] * bv.w;
            }
        }
        __syncthreads();
    }
    #pragma unroll
    for (int m = 0; m < 8; m++) {
        *(float4*)(out + (size_t)(b * 64 + tmg * 8 + m) * NPIX + n0 + tng * 4) =
            make_float4(acc[m][0], acc[m][1], acc[m][2], acc[m][3]);
    }
}

// ---------------- launch ----------------
extern "C" void kernel_launch(void* const* d_in, const int* in_sizes, int n_in,
                              void* d_out, int out_size) {
    (void)in_sizes; (void)n_in; (void)out_size;
    const float* x     = (const float*)d_in[0];
    const float* W_in  = (const float*)d_in[1];
    const float* W_dw  = (const float*)d_in[2];
    const float* quant = (const float*)d_in[3];
    const float* W_out = (const float*)d_in[4];
    float* out = (float*)d_out;

    cudaFuncSetAttribute(k_fuse, cudaFuncAttributeMaxDynamicSharedMemorySize,
                         96 * 256 * 4);

    k_transpose<<<85, 256>>>(W_in, W_out);
    k_dct<<<dim3(32, 64, 4), 256>>>(x);
    k_proj_in<<<dim3(512, 6, 4), 256>>>(quant);
    k_fuse<<<dim3(8, 170, 4), 384, 96 * 256 * 4>>>(W_dw);
    k_proj_out<<<dim3(512, 4), 256>>>(out);
}

// round 11
// speedup vs baseline: 1.5311x; 1.0573x over previous
#include <cuda_runtime.h>
#include <math.h>

#define BB   4
#define CIN  64
#define C2   340
#define HID  170
#define HH   256
#define WW   256
#define NPIX 65536   /* 256*256 */

// ---------------- scratch (device globals; no allocations) ----------------
__device__ float g_xd[BB * CIN * NPIX];          // DCT(x): 67 MB
__device__ float g_yq[BB * C2  * NPIX];          // quant * (W_in @ DCT(x)): 356 MB
__device__ float g_g [BB * HID * NPIX];          // gelu(x1)*x2: 178 MB
__device__ float g_Wt [64  * 384];               // W_in^T  [k][m], stride 384 (zero padded)
__device__ float g_Wot[170 * 64];                // W_out^T [k][m]

__device__ __forceinline__ unsigned f2tf(float f) {
    unsigned u;
    asm("cvt.rna.tf32.f32 %0, %1;" : "=r"(u) : "f"(f));
    return u;
}

// ---------------- tiny transpose of the weight matrices ----------------
__global__ void k_transpose(const float* __restrict__ W_in,
                            const float* __restrict__ W_out) {
    int t = blockIdx.x * blockDim.x + threadIdx.x;
    if (t < C2 * CIN) {               // W_in [340][64] -> g_Wt [64][384]
        int m = t / CIN, k = t % CIN;
        g_Wt[k * 384 + m] = W_in[t];
    }
    if (t < 64 * HID) {               // W_out [64][170] -> g_Wot [170][64]
        int m = t / HID, k = t % HID;
        g_Wot[k * 64 + m] = W_out[t];
    }
}

// ---------------- K1: per-patch 2D DCT, register-resident ----------------
// Each thread owns one 8x8 patch: gmem -> regs -> M @ X @ M^T -> gmem.
__global__ __launch_bounds__(256) void k_dct(const float* __restrict__ x) {
    __shared__ float Ms[64];
    int tid = threadIdx.x;
    if (tid < 64) {
        int i = tid >> 3, j = tid & 7;
        Ms[tid] = (i == 0) ? 0.35355339059327373f
                           : 0.5f * cospif((float)(i * (2 * j + 1)) * (1.0f / 16.0f));
    }
    __syncthreads();
    int pr = blockIdx.x * 8 + (tid >> 5);          // patch row 0..31
    int pc = tid & 31;                             // patch col 0..31
    int c = blockIdx.y, b = blockIdx.z;
    const float* src = x + ((size_t)(b * CIN + c) * HH + pr * 8) * WW + pc * 8;
    float v[8][8];
    #pragma unroll
    for (int p = 0; p < 8; p++) {
        float4 a = *(const float4*)(src + (size_t)p * WW);
        float4 d = *(const float4*)(src + (size_t)p * WW + 4);
        v[p][0] = a.x; v[p][1] = a.y; v[p][2] = a.z; v[p][3] = a.w;
        v[p][4] = d.x; v[p][5] = d.y; v[p][6] = d.z; v[p][7] = d.w;
    }
    // column transform: v[:,j] <- M @ v[:,j]
    #pragma unroll
    for (int j = 0; j < 8; j++) {
        float u[8];
        #pragma unroll
        for (int p = 0; p < 8; p++) u[p] = v[p][j];
        #pragma unroll
        for (int i = 0; i < 8; i++) {
            float s = 0.f;
            #pragma unroll
            for (int p = 0; p < 8; p++) s += Ms[i * 8 + p] * u[p];
            v[i][j] = s;
        }
    }
    // row transform: v[i,:] <- v[i,:] @ M^T
    float* dst = g_xd + ((size_t)(b * CIN + c) * HH + pr * 8) * WW + pc * 8;
    #pragma unroll
    for (int i = 0; i < 8; i++) {
        float u[8];
        #pragma unroll
        for (int q = 0; q < 8; q++) u[q] = v[i][q];
        float y[8];
        #pragma unroll
        for (int j = 0; j < 8; j++) {
            float s = 0.f;
            #pragma unroll
            for (int q = 0; q < 8; q++) s += u[q] * Ms[j * 8 + q];
            y[j] = s;
        }
        *(float4*)(dst + (size_t)i * WW)     = make_float4(y[0], y[1], y[2], y[3]);
        *(float4*)(dst + (size_t)i * WW + 4) = make_float4(y[4], y[5], y[6], y[7]);
    }
}

// ---------------- K2: yq = quant * (W_in @ xd), tf32 mma.sync ----------------
// Block tile 64(M) x 128(N) x 64(K). 8 warps in 2(M) x 4(N) grid, each warp a
// 32x32 tile via m16n8k8 tf32 HMMA, fp32 accumulate, quant in epilogue.
// Grid (6, 512, 4): m-tile fastest so the 6 blocks sharing a B tile hit L2.
#define AS_STRIDE 68
#define BS_STRIDE 132
__global__ __launch_bounds__(256) void k_proj_in(const float* __restrict__ quant) {
    __shared__ unsigned As[64 * AS_STRIDE];   // [k][m], tf32, padded
    __shared__ unsigned Bs[64 * BS_STRIDE];   // [k][n], tf32, padded
    int m0 = blockIdx.x * 64;
    int n0 = blockIdx.y * 128;
    int b  = blockIdx.z;
    int tid = threadIdx.x;

    for (int i = tid; i < 64 * 16; i += 256) {            // A tile
        int k = i >> 4, m4 = (i & 15) * 4;
        float4 w = *(const float4*)(g_Wt + k * 384 + m0 + m4);
        unsigned* d = &As[k * AS_STRIDE + m4];
        d[0] = f2tf(w.x); d[1] = f2tf(w.y); d[2] = f2tf(w.z); d[3] = f2tf(w.w);
    }
    const float* Bbase = g_xd + (size_t)b * CIN * NPIX + n0;
    for (int i = tid; i < 64 * 32; i += 256) {            // B tile
        int k = i >> 5, n4 = (i & 31) * 4;
        float4 w = *(const float4*)(Bbase + (size_t)k * NPIX + n4);
        unsigned* d = &Bs[k * BS_STRIDE + n4];
        d[0] = f2tf(w.x); d[1] = f2tf(w.y); d[2] = f2tf(w.z); d[3] = f2tf(w.w);
    }
    __syncthreads();

    int warp = tid >> 5, lane = tid & 31;
    int wm = warp & 1, wn = warp >> 1;                    // 2 x 4 warp grid
    int g  = lane >> 2, tg = lane & 3;
    int mb = wm * 32, nb = wn * 32;

    float c[2][4][4];
    #pragma unroll
    for (int mi = 0; mi < 2; mi++)
        #pragma unroll
        for (int ni = 0; ni < 4; ni++)
            #pragma unroll
            for (int t = 0; t < 4; t++) c[mi][ni][t] = 0.f;

    #pragma unroll
    for (int ks = 0; ks < 8; ks++) {
        int k0 = ks * 8;
        unsigned a[2][4];
        #pragma unroll
        for (int mi = 0; mi < 2; mi++) {
            int mloc = mb + mi * 16;
            a[mi][0] = As[(k0 + tg)     * AS_STRIDE + mloc + g];
            a[mi][1] = As[(k0 + tg)     * AS_STRIDE + mloc + g + 8];
            a[mi][2] = As[(k0 + tg + 4) * AS_STRIDE + mloc + g];
            a[mi][3] = As[(k0 + tg + 4) * AS_STRIDE + mloc + g + 8];
        }
        #pragma unroll
        for (int ni = 0; ni < 4; ni++) {
            int nloc = nb + ni * 8;
            unsigned b0 = Bs[(k0 + tg)     * BS_STRIDE + nloc + g];
            unsigned b1 = Bs[(k0 + tg + 4) * BS_STRIDE + nloc + g];
            #pragma unroll
            for (int mi = 0; mi < 2; mi++) {
                asm("mma.sync.aligned.m16n8k8.row.col.f32.tf32.tf32.f32 "
                    "{%0,%1,%2,%3}, {%4,%5,%6,%7}, {%8,%9}, {%0,%1,%2,%3};"
                    : "+f"(c[mi][ni][0]), "+f"(c[mi][ni][1]),
                      "+f"(c[mi][ni][2]), "+f"(c[mi][ni][3])
                    : "r"(a[mi][0]), "r"(a[mi][1]), "r"(a[mi][2]), "r"(a[mi][3]),
                      "r"(b0), "r"(b1));
            }
        }
    }

    // epilogue: quant multiply + store. fi = image row & 7 (shared by tile).
    int fi = (n0 >> 8) & 7;
    float* outb = g_yq + (size_t)b * C2 * NPIX + n0;
    #pragma unroll
    for (int mi = 0; mi < 2; mi++) {
        #pragma unroll
        for (int half = 0; half < 2; half++) {            // c0/c1 then c2/c3
            int cc = m0 + mb + mi * 16 + g + half * 8;
            if (cc < C2) {
                const float* qrow = quant + cc * 64 + fi * 8;
                float* orow = outb + (size_t)cc * NPIX;
                #pragma unroll
                for (int ni = 0; ni < 4; ni++) {
                    int nloc = nb + ni * 8 + 2 * tg;
                    int fj = 2 * tg;                      // (n0 multiple of 128)
                    float2 o;
                    o.x = c[mi][ni][half * 2]     * qrow[fj];
                    o.y = c[mi][ni][half * 2 + 1] * qrow[fj + 1];
                    *(float2*)(orow + nloc) = o;
                }
            }
        }
    }
}

// ---------------- K3: fused IDCT + depthwise 3x3 + GLU(gelu) -> g ----------------
// Register-resident per-patch IDCT (R10), unchanged.
__global__ __launch_bounds__(384) void k_fuse(const float* __restrict__ W_dw) {
    extern __shared__ float sm[];                  // 96 rows * 256 floats = 96 KB
    __shared__ float Ms[64];
    int tid = threadIdx.x;
    if (tid < 64) {
        int i = tid >> 3, j = tid & 7;
        Ms[tid] = (i == 0) ? 0.35355339059327373f
                           : 0.5f * cospif((float)(i * (2 * j + 1)) * (1.0f / 16.0f));
    }
    __syncthreads();

    int yt = blockIdx.x, c = blockIdx.y, b = blockIdx.z;
    int y0 = yt * 32;

    {
        int ch  = tid / 192;
        int rem = tid - ch * 192;
        int pr  = rem >> 5;
        int pc  = rem & 31;
        const float* src = g_yq + (size_t)(b * C2 + c + ch * HID) * NPIX;
        int gy0 = y0 - 8 + pr * 8;
        float v[8][8];
        if (gy0 >= 0 && gy0 < HH) {
            #pragma unroll
            for (int p = 0; p < 8; p++) {
                const float* row = src + (size_t)(gy0 + p) * WW + pc * 8;
                float4 a = *(const float4*)row;
                float4 d = *(const float4*)(row + 4);
                v[p][0] = a.x; v[p][1] = a.y; v[p][2] = a.z; v[p][3] = a.w;
                v[p][4] = d.x; v[p][5] = d.y; v[p][6] = d.z; v[p][7] = d.w;
            }
            #pragma unroll
            for (int j = 0; j < 8; j++) {
                float u[8];
                #pragma unroll
                for (int p = 0; p < 8; p++) u[p] = v[p][j];
                #pragma unroll
                for (int r = 0; r < 8; r++) {
                    float s = 0.f;
                    #pragma unroll
                    for (int p = 0; p < 8; p++) s += Ms[p * 8 + r] * u[p];
                    v[r][j] = s;
                }
            }
            #pragma unroll
            for (int r = 0; r < 8; r++) {
                float u[8];
                #pragma unroll
                for (int q = 0; q < 8; q++) u[q] = v[r][q];
                #pragma unroll
                for (int j = 0; j < 8; j++) {
                    float s = 0.f;
                    #pragma unroll
                    for (int q = 0; q < 8; q++) s += u[q] * Ms[q * 8 + j];
                    v[r][j] = s;
                }
            }
        } else {
            #pragma unroll
            for (int p = 0; p < 8; p++)
                #pragma unroll
                for (int j = 0; j < 8; j++) v[p][j] = 0.f;
        }
        float* dst = &sm[(ch * 48 + pr * 8) * 256 + pc * 8];
        #pragma unroll
        for (int r = 0; r < 8; r++) {
            *(float4*)(dst + r * 256)     = make_float4(v[r][0], v[r][1], v[r][2], v[r][3]);
            *(float4*)(dst + r * 256 + 4) = make_float4(v[r][4], v[r][5], v[r][6], v[r][7]);
        }
    }
    __syncthreads();

    float wA[9], wB[9];
    #pragma unroll
    for (int t = 0; t < 9; t++) wA[t] = __ldg(&W_dw[c * 9 + t]);
    #pragma unroll
    for (int t = 0; t < 9; t++) wB[t] = __ldg(&W_dw[(c + HID) * 9 + t]);

    float* gdst = g_g + (size_t)(b * HID + c) * NPIX + (size_t)y0 * WW;
    for (int g4 = tid; g4 < 32 * 64; g4 += 384) {
        int r = g4 >> 6, w0 = (g4 & 63) * 4;
        float s1[4] = {0.f, 0.f, 0.f, 0.f};
        float s2[4] = {0.f, 0.f, 0.f, 0.f};
        #pragma unroll
        for (int dy = 0; dy < 3; dy++) {
            const float* rowA = &sm[(r + 7 + dy) * 256];
            const float* rowB = rowA + 48 * 256;
            float vA[6], vB[6];
            vA[0] = (w0 == 0)   ? 0.f : rowA[w0 - 1];
            vA[1] = rowA[w0];     vA[2] = rowA[w0 + 1];
            vA[3] = rowA[w0 + 2]; vA[4] = rowA[w0 + 3];
            vA[5] = (w0 == 252) ? 0.f : rowA[w0 + 4];
            vB[0] = (w0 == 0)   ? 0.f : rowB[w0 - 1];
            vB[1] = rowB[w0];     vB[2] = rowB[w0 + 1];
            vB[3] = rowB[w0 + 2]; vB[4] = rowB[w0 + 3];
            vB[5] = (w0 == 252) ? 0.f : rowB[w0 + 4];
            #pragma unroll
            for (int dx = 0; dx < 3; dx++) {
                float wa = wA[dy * 3 + dx], wb = wB[dy * 3 + dx];
                #pragma unroll
                for (int j = 0; j < 4; j++) {
                    s1[j] += wa * vA[j + dx];
                    s2[j] += wb * vB[j + dx];
                }
            }
        }
        float o[4];
        #pragma unroll
        for (int j = 0; j < 4; j++)
            o[j] = 0.5f * s1[j] * (1.f + erff(s1[j] * 0.70710678118654752f)) * s2[j];
        *(float4*)&gdst[r * 256 + w0] = make_float4(o[0], o[1], o[2], o[3]);
    }
}

// ---------------- K4: out = W_out @ g  (GEMM M=64, K=170, N=65536 per batch)
__global__ __launch_bounds__(256) void k_proj_out(float* __restrict__ out) {
    __shared__ float As[34][64];
    __shared__ float Bs[34][128];
    int n0 = blockIdx.x * 128, b = blockIdx.y, tid = threadIdx.x;
    int tmg = tid >> 5, tng = tid & 31;
    float acc[8][4];
    #pragma unroll
    for (int m = 0; m < 8; m++) { acc[m][0] = acc[m][1] = acc[m][2] = acc[m][3] = 0.f; }

    for (int kk = 0; kk < HID; kk += 34) {
        for (int i = tid; i < 34 * 16; i += 256) {
            int k = i >> 4, m4 = i & 15;
            *(float4*)&As[k][m4 * 4] = *(const float4*)(g_Wot + (kk + k) * 64 + m4 * 4);
        }
        for (int i = tid; i < 34 * 32; i += 256) {
            int k = i >> 5, n4 = i & 31;
            *(float4*)&Bs[k][n4 * 4] =
                *(const float4*)(g_g + (size_t)(b * HID + kk + k) * NPIX + n0 + n4 * 4);
        }
        __syncthreads();
        #pragma unroll
        for (int k = 0; k < 34; k++) {
            float4 bv = *(float4*)&Bs[k][tng * 4];
            float4 a0 = *(float4*)&As[k][tmg * 8];
            float4 a1 = *(float4*)&As[k][tmg * 8 + 4];
            float a[8] = {a0.x, a0.y, a0.z, a0.w, a1.x, a1.y, a1.z, a1.w};
            #pragma unroll
            for (int m = 0; m < 8; m++) {
                acc[m][0] += a[m] * bv.x; acc[m][1] += a[m] * bv.y;
                acc[m][2] += a[m] * bv.z; acc[m][3] += a[m] * bv.w;
            }
        }
        __syncthreads();
    }
    #pragma unroll
    for (int m = 0; m < 8; m++) {
        *(float4*)(out + (size_t)(b * 64 + tmg * 8 + m) * NPIX + n0 + tng * 4) =
            make_float4(acc[m][0], acc[m][1], acc[m][2], acc[m][3]);
    }
}

// ---------------- launch ----------------
extern "C" void kernel_launch(void* const* d_in, const int* in_sizes, int n_in,
                              void* d_out, int out_size) {
    (void)in_sizes; (void)n_in; (void)out_size;
    const float* x     = (const float*)d_in[0];
    const float* W_in  = (const float*)d_in[1];
    const float* W_dw  = (const float*)d_in[2];
    const float* quant = (const float*)d_in[3];
    const float* W_out = (const float*)d_in[4];
    float* out = (float*)d_out;

    cudaFuncSetAttribute(k_fuse, cudaFuncAttributeMaxDynamicSharedMemorySize,
                         96 * 256 * 4);

    k_transpose<<<85, 256>>>(W_in, W_out);
    k_dct<<<dim3(4, 64, 4), 256>>>(x);
    k_proj_in<<<dim3(6, 512, 4), 256>>>(quant);
    k_fuse<<<dim3(8, 170, 4), 384, 96 * 256 * 4>>>(W_dw);
    k_proj_out<<<dim3(512, 4), 256>>>(out);
}